// round 1
// baseline (speedup 1.0000x reference)
#include <cuda_runtime.h>

#define C 128
#define TILE 64
#define THREADS 256
#define RPW 8          // rows per warp (8 warps * 8 rows = 64)
#define EPSF 1e-8f

// Precomputed score matrices M = (Wq @ Wk^T) / sqrt(C), per branch.
__device__ float g_Mm[C * C];
__device__ float g_Md[C * C];

// ---------------------------------------------------------------------------
// K0: M[i][i'] = sum_j Wq[i][j] * Wk[i'][j] / sqrt(C)
// grid (128, 2), block 128. Tiny (2 x 2M MACs), cost is noise.
// ---------------------------------------------------------------------------
__global__ void precompute_M_kernel(const float* __restrict__ Wq_m,
                                    const float* __restrict__ Wk_m,
                                    const float* __restrict__ Wq_d,
                                    const float* __restrict__ Wk_d) {
    const float* Wq = blockIdx.y ? Wq_d : Wq_m;
    const float* Wk = blockIdx.y ? Wk_d : Wk_m;
    float* M = blockIdx.y ? g_Md : g_Mm;
    int i = blockIdx.x, t = threadIdx.x;
    __shared__ float qrow[C];
    qrow[t] = Wq[i * C + t];
    __syncthreads();
    const float* wkr = Wk + t * C;
    float acc = 0.f;
#pragma unroll 8
    for (int j = 0; j < C; j++) acc += qrow[j] * wkr[j];
    M[i * C + t] = acc * 0.08838834764831845f;  // 1/sqrt(128)
}

// ---------------------------------------------------------------------------
// K1: fully fused per-row pipeline.
// SMEM: em/ed/x0/x1 tiles (64x128 f32 each) + one 128x128 weight slot + W2.
// ---------------------------------------------------------------------------
__global__ void __launch_bounds__(THREADS, 1)
fused_kernel(const float* __restrict__ em, const float* __restrict__ ed,
             const float* __restrict__ W_gcn, const float* __restrict__ Wv_m,
             const float* __restrict__ Wv_d, const float* __restrict__ W1,
             const float* __restrict__ W2, float* __restrict__ out) {
    extern __shared__ float sm[];
    float* sEM = sm;                 // TILE*C
    float* sED = sEM + TILE * C;     // TILE*C
    float* sX0 = sED + TILE * C;     // TILE*C
    float* sX1 = sX0 + TILE * C;     // TILE*C
    float* sW  = sX1 + TILE * C;     // C*C
    float* sW2 = sW + C * C;         // C

    const int tid = threadIdx.x;
    const int lane = tid & 31;
    const int w = tid >> 5;
    const int r0 = w * RPW;
    const long base = (long)blockIdx.x * TILE;

    // ---- load em / ed tile (vectorized, coalesced) ----
    {
        const float4* ge = (const float4*)(em + base * C);
        const float4* gd = (const float4*)(ed + base * C);
        float4* se = (float4*)sEM;
        float4* sd = (float4*)sED;
        for (int i = tid; i < TILE * C / 4; i += THREADS) {
            se[i] = ge[i];
            sd[i] = gd[i];
        }
        if (tid < C) sW2[tid] = W2[tid];
    }
    __syncthreads();

    // ---- per-row adjacency scalars a, b ----
    float aS[RPW], bS[RPW];
#pragma unroll
    for (int rr = 0; rr < RPW; rr++) {
        const float* pe = sEM + (r0 + rr) * C;
        const float* pd = sED + (r0 + rr) * C;
        float sa = 0.f, q0 = 0.f, q1 = 0.f, dp = 0.f;
#pragma unroll
        for (int q = 0; q < 4; q++) {
            int k = lane + 32 * q;
            float e = pe[k], d = pd[k];
            sa += fabsf(e - d);
            q0 += e * e;
            q1 += d * d;
            dp += e * d;
        }
#pragma unroll
        for (int o = 16; o; o >>= 1) {
            sa += __shfl_xor_sync(~0u, sa, o);
            q0 += __shfl_xor_sync(~0u, q0, o);
            q1 += __shfl_xor_sync(~0u, q1, o);
            dp += __shfl_xor_sync(~0u, dp, o);
        }
        float m = sa;  // lrelu(m) == m since m >= 0
        float cosv = dp / (sqrtf(q0 + EPSF) * sqrtf(q1 + EPSF));
        float cp = cosv > 0.f ? cosv : 0.01f * cosv;
        float a1 = 1.f / (1.f + cp), b1 = cp / (1.f + cp);
        float a3 = 1.f / (1.f + m),  b3 = m  / (1.f + m);
        aS[rr] = fminf(a1, a3);
        bS[rr] = fminf(b1, b3);
    }

    // weight stager: sync, copy 64KB into the shared slot, sync
    auto load_w = [&](const float* g) {
        __syncthreads();
        float4* d4 = (float4*)sW;
        const float4* s4 = (const float4*)g;
        for (int i = tid; i < C * C / 4; i += THREADS) d4[i] = s4[i];
        __syncthreads();
    };

    // ---- GCN: g0 = em@W, g1 = ed@W; x1_* = relu(pL @ g) + x0 ----
    load_w(W_gcn);
    {
        float A0[RPW][4] = {}, A1[RPW][4] = {};
        const float4* w4 = (const float4*)sW;
#pragma unroll 2
        for (int k = 0; k < C; k++) {
            float4 wv = w4[k * 32 + lane];
#pragma unroll
            for (int rr = 0; rr < RPW; rr++) {
                float e = sEM[(r0 + rr) * C + k];
                float d = sED[(r0 + rr) * C + k];
                A0[rr][0] += e * wv.x; A0[rr][1] += e * wv.y;
                A0[rr][2] += e * wv.z; A0[rr][3] += e * wv.w;
                A1[rr][0] += d * wv.x; A1[rr][1] += d * wv.y;
                A1[rr][2] += d * wv.z; A1[rr][3] += d * wv.w;
            }
        }
        int j = lane * 4;
#pragma unroll
        for (int rr = 0; rr < RPW; rr++) {
            float4 e4 = *(const float4*)(sEM + (r0 + rr) * C + j);
            float4 d4 = *(const float4*)(sED + (r0 + rr) * C + j);
            float a = aS[rr], b = bS[rr];
            float4 x0, x1;
            x0.x = fmaxf(a * A0[rr][0] + b * A1[rr][0], 0.f) + e4.x;
            x0.y = fmaxf(a * A0[rr][1] + b * A1[rr][1], 0.f) + e4.y;
            x0.z = fmaxf(a * A0[rr][2] + b * A1[rr][2], 0.f) + e4.z;
            x0.w = fmaxf(a * A0[rr][3] + b * A1[rr][3], 0.f) + e4.w;
            x1.x = fmaxf(b * A0[rr][0] + a * A1[rr][0], 0.f) + d4.x;
            x1.y = fmaxf(b * A0[rr][1] + a * A1[rr][1], 0.f) + d4.y;
            x1.z = fmaxf(b * A0[rr][2] + a * A1[rr][2], 0.f) + d4.z;
            x1.w = fmaxf(b * A0[rr][3] + a * A1[rr][3], 0.f) + d4.w;
            *(float4*)(sX0 + (r0 + rr) * C + j) = x0;
            *(float4*)(sX1 + (r0 + rr) * C + j) = x1;
        }
        __syncwarp();
    }

    // ---- attention branch (shared code for m / d) ----
    // t = x_last @ M; s0 = t.x_first; s1 = t.x_last; u = w0*x_first + w1*x_last (in place)
    auto attn_scores_u = [&](const float* sFirst, float* sLast) {
        float T[RPW][4] = {};
        const float4* w4 = (const float4*)sW;
#pragma unroll 2
        for (int k = 0; k < C; k++) {
            float4 wv = w4[k * 32 + lane];
#pragma unroll
            for (int rr = 0; rr < RPW; rr++) {
                float x = sLast[(r0 + rr) * C + k];
                T[rr][0] += x * wv.x; T[rr][1] += x * wv.y;
                T[rr][2] += x * wv.z; T[rr][3] += x * wv.w;
            }
        }
        int j = lane * 4;
#pragma unroll
        for (int rr = 0; rr < RPW; rr++) {
            float4 f4 = *(const float4*)(sFirst + (r0 + rr) * C + j);
            float4 l4 = *(const float4*)(sLast + (r0 + rr) * C + j);
            float s0 = T[rr][0] * f4.x + T[rr][1] * f4.y + T[rr][2] * f4.z + T[rr][3] * f4.w;
            float s1 = T[rr][0] * l4.x + T[rr][1] * l4.y + T[rr][2] * l4.z + T[rr][3] * l4.w;
#pragma unroll
            for (int o = 16; o; o >>= 1) {
                s0 += __shfl_xor_sync(~0u, s0, o);
                s1 += __shfl_xor_sync(~0u, s1, o);
            }
            float mx = fmaxf(s0, s1);
            float e0 = expf(s0 - mx), e1 = expf(s1 - mx);
            float inv = 1.f / (e0 + e1);
            float w0 = e0 * inv, w1 = e1 * inv;
            float4 u;
            u.x = w0 * f4.x + w1 * l4.x;
            u.y = w0 * f4.y + w1 * l4.y;
            u.z = w0 * f4.z + w1 * l4.z;
            u.w = w0 * f4.w + w1 * l4.w;
            *(float4*)(sLast + (r0 + rr) * C + j) = u;
        }
        __syncwarp();
    };

    // u @ Wv -> overwrite sBuf rows with LA output
    auto matvec_inplace = [&](float* sBuf) {
        float Acc[RPW][4] = {};
        const float4* w4 = (const float4*)sW;
#pragma unroll 2
        for (int k = 0; k < C; k++) {
            float4 wv = w4[k * 32 + lane];
#pragma unroll
            for (int rr = 0; rr < RPW; rr++) {
                float x = sBuf[(r0 + rr) * C + k];
                Acc[rr][0] += x * wv.x; Acc[rr][1] += x * wv.y;
                Acc[rr][2] += x * wv.z; Acc[rr][3] += x * wv.w;
            }
        }
        __syncwarp();
        int j = lane * 4;
#pragma unroll
        for (int rr = 0; rr < RPW; rr++) {
            *(float4*)(sBuf + (r0 + rr) * C + j) =
                make_float4(Acc[rr][0], Acc[rr][1], Acc[rr][2], Acc[rr][3]);
        }
        __syncwarp();
    };

    // m-branch: layers [em, x1_0], query = x1_0
    load_w(g_Mm);
    attn_scores_u(sEM, sX0);
    load_w(Wv_m);
    matvec_inplace(sX0);   // sX0 now holds mLA

    // d-branch: layers [ed, x1_1], query = x1_1
    load_w(g_Md);
    attn_scores_u(sED, sX1);
    load_w(Wv_d);
    matvec_inplace(sX1);   // sX1 now holds dLA

    // ---- head: h = relu((mLA*dLA) @ W1); pre = h . W2; sigmoid ----
    load_w(W1);
    {
        float H[RPW][4] = {};
        const float4* w4 = (const float4*)sW;
#pragma unroll 2
        for (int k = 0; k < C; k++) {
            float4 wv = w4[k * 32 + lane];
#pragma unroll
            for (int rr = 0; rr < RPW; rr++) {
                float ne = sX0[(r0 + rr) * C + k] * sX1[(r0 + rr) * C + k];
                H[rr][0] += ne * wv.x; H[rr][1] += ne * wv.y;
                H[rr][2] += ne * wv.z; H[rr][3] += ne * wv.w;
            }
        }
        int j = lane * 4;
#pragma unroll
        for (int rr = 0; rr < RPW; rr++) {
            float p = fmaxf(H[rr][0], 0.f) * sW2[j]
                    + fmaxf(H[rr][1], 0.f) * sW2[j + 1]
                    + fmaxf(H[rr][2], 0.f) * sW2[j + 2]
                    + fmaxf(H[rr][3], 0.f) * sW2[j + 3];
#pragma unroll
            for (int o = 16; o; o >>= 1) p += __shfl_xor_sync(~0u, p, o);
            if (lane == 0)
                out[base + r0 + rr] = 1.f / (1.f + expf(-p));
        }
    }
}

// ---------------------------------------------------------------------------
extern "C" void kernel_launch(void* const* d_in, const int* in_sizes, int n_in,
                              void* d_out, int out_size) {
    const float* em    = (const float*)d_in[0];
    const float* ed    = (const float*)d_in[1];
    const float* W_gcn = (const float*)d_in[2];
    const float* Wq_m  = (const float*)d_in[3];
    const float* Wk_m  = (const float*)d_in[4];
    const float* Wv_m  = (const float*)d_in[5];
    const float* Wq_d  = (const float*)d_in[6];
    const float* Wk_d  = (const float*)d_in[7];
    const float* Wv_d  = (const float*)d_in[8];
    const float* W1    = (const float*)d_in[9];
    const float* W2    = (const float*)d_in[10];
    float* out = (float*)d_out;

    const int B = in_sizes[0] / C;           // 262144
    const int smem_bytes = (4 * TILE * C + C * C + C) * (int)sizeof(float);  // 197120

    precompute_M_kernel<<<dim3(C, 2), C>>>(Wq_m, Wk_m, Wq_d, Wk_d);

    cudaFuncSetAttribute(fused_kernel,
                         cudaFuncAttributeMaxDynamicSharedMemorySize, smem_bytes);
    fused_kernel<<<B / TILE, THREADS, smem_bytes>>>(em, ed, W_gcn, Wv_m, Wv_d,
                                                    W1, W2, out);
}

// round 2
// speedup vs baseline: 1.0024x; 1.0024x over previous
#include <cuda_runtime.h>

#define C 128
#define TILE 64
#define THREADS 256
#define RPW 8          // rows per warp (8 warps * 8 rows = 64)
#define EPSF 1e-8f

// Precomputed score matrices M = (Wq @ Wk^T) / sqrt(C), per branch.
__device__ float g_Mm[C * C];
__device__ float g_Md[C * C];

// ---------------------------------------------------------------------------
// K0: M[i][i'] = sum_j Wq[i][j] * Wk[i'][j] / sqrt(C)
// grid (128, 2), block 128. Tiny (2 x 2M MACs), cost is noise.
// ---------------------------------------------------------------------------
__global__ void precompute_M_kernel(const float* __restrict__ Wq_m,
                                    const float* __restrict__ Wk_m,
                                    const float* __restrict__ Wq_d,
                                    const float* __restrict__ Wk_d) {
    const float* Wq = blockIdx.y ? Wq_d : Wq_m;
    const float* Wk = blockIdx.y ? Wk_d : Wk_m;
    float* M = blockIdx.y ? g_Md : g_Mm;
    int i = blockIdx.x, t = threadIdx.x;
    __shared__ float qrow[C];
    qrow[t] = Wq[i * C + t];
    __syncthreads();
    const float* wkr = Wk + t * C;
    float acc = 0.f;
#pragma unroll 8
    for (int j = 0; j < C; j++) acc += qrow[j] * wkr[j];
    M[i * C + t] = acc * 0.08838834764831845f;  // 1/sqrt(128)
}

// ---------------------------------------------------------------------------
// K1: fully fused per-row pipeline.
// SMEM: em/ed/x0/x1 tiles (64x128 f32 each) + one 128x128 weight slot + W2.
// ---------------------------------------------------------------------------
__global__ void __launch_bounds__(THREADS, 1)
fused_kernel(const float* __restrict__ em, const float* __restrict__ ed,
             const float* __restrict__ W_gcn, const float* __restrict__ Wv_m,
             const float* __restrict__ Wv_d, const float* __restrict__ W1,
             const float* __restrict__ W2, float* __restrict__ out) {
    extern __shared__ float sm[];
    float* sEM = sm;                 // TILE*C
    float* sED = sEM + TILE * C;     // TILE*C
    float* sX0 = sED + TILE * C;     // TILE*C
    float* sX1 = sX0 + TILE * C;     // TILE*C
    float* sW  = sX1 + TILE * C;     // C*C
    float* sW2 = sW + C * C;         // C

    const int tid = threadIdx.x;
    const int lane = tid & 31;
    const int w = tid >> 5;
    const int r0 = w * RPW;
    const long base = (long)blockIdx.x * TILE;

    // ---- load em / ed tile (vectorized, coalesced) ----
    {
        const float4* ge = (const float4*)(em + base * C);
        const float4* gd = (const float4*)(ed + base * C);
        float4* se = (float4*)sEM;
        float4* sd = (float4*)sED;
        for (int i = tid; i < TILE * C / 4; i += THREADS) {
            se[i] = ge[i];
            sd[i] = gd[i];
        }
        if (tid < C) sW2[tid] = W2[tid];
    }
    __syncthreads();

    // ---- per-row adjacency scalars a, b ----
    float aS[RPW], bS[RPW];
#pragma unroll
    for (int rr = 0; rr < RPW; rr++) {
        const float* pe = sEM + (r0 + rr) * C;
        const float* pd = sED + (r0 + rr) * C;
        float sa = 0.f, q0 = 0.f, q1 = 0.f, dp = 0.f;
#pragma unroll
        for (int q = 0; q < 4; q++) {
            int k = lane + 32 * q;
            float e = pe[k], d = pd[k];
            sa += fabsf(e - d);
            q0 += e * e;
            q1 += d * d;
            dp += e * d;
        }
#pragma unroll
        for (int o = 16; o; o >>= 1) {
            sa += __shfl_xor_sync(~0u, sa, o);
            q0 += __shfl_xor_sync(~0u, q0, o);
            q1 += __shfl_xor_sync(~0u, q1, o);
            dp += __shfl_xor_sync(~0u, dp, o);
        }
        float m = sa;  // lrelu(m) == m since m >= 0
        float cosv = dp / (sqrtf(q0 + EPSF) * sqrtf(q1 + EPSF));
        float cp = cosv > 0.f ? cosv : 0.01f * cosv;
        float a1 = 1.f / (1.f + cp), b1 = cp / (1.f + cp);
        float a3 = 1.f / (1.f + m),  b3 = m  / (1.f + m);
        aS[rr] = fminf(a1, a3);
        bS[rr] = fminf(b1, b3);
    }

    // weight stager: sync, copy 64KB into the shared slot, sync
    auto load_w = [&](const float* g) {
        __syncthreads();
        float4* d4 = (float4*)sW;
        const float4* s4 = (const float4*)g;
        for (int i = tid; i < C * C / 4; i += THREADS) d4[i] = s4[i];
        __syncthreads();
    };

    // ---- GCN: g0 = em@W, g1 = ed@W; x1_* = relu(pL @ g) + x0 ----
    load_w(W_gcn);
    {
        float A0[RPW][4] = {}, A1[RPW][4] = {};
        const float4* w4 = (const float4*)sW;
#pragma unroll 2
        for (int k = 0; k < C; k++) {
            float4 wv = w4[k * 32 + lane];
#pragma unroll
            for (int rr = 0; rr < RPW; rr++) {
                float e = sEM[(r0 + rr) * C + k];
                float d = sED[(r0 + rr) * C + k];
                A0[rr][0] += e * wv.x; A0[rr][1] += e * wv.y;
                A0[rr][2] += e * wv.z; A0[rr][3] += e * wv.w;
                A1[rr][0] += d * wv.x; A1[rr][1] += d * wv.y;
                A1[rr][2] += d * wv.z; A1[rr][3] += d * wv.w;
            }
        }
        int j = lane * 4;
#pragma unroll
        for (int rr = 0; rr < RPW; rr++) {
            float4 e4 = *(const float4*)(sEM + (r0 + rr) * C + j);
            float4 d4 = *(const float4*)(sED + (r0 + rr) * C + j);
            float a = aS[rr], b = bS[rr];
            float4 x0, x1;
            x0.x = fmaxf(a * A0[rr][0] + b * A1[rr][0], 0.f) + e4.x;
            x0.y = fmaxf(a * A0[rr][1] + b * A1[rr][1], 0.f) + e4.y;
            x0.z = fmaxf(a * A0[rr][2] + b * A1[rr][2], 0.f) + e4.z;
            x0.w = fmaxf(a * A0[rr][3] + b * A1[rr][3], 0.f) + e4.w;
            x1.x = fmaxf(b * A0[rr][0] + a * A1[rr][0], 0.f) + d4.x;
            x1.y = fmaxf(b * A0[rr][1] + a * A1[rr][1], 0.f) + d4.y;
            x1.z = fmaxf(b * A0[rr][2] + a * A1[rr][2], 0.f) + d4.z;
            x1.w = fmaxf(b * A0[rr][3] + a * A1[rr][3], 0.f) + d4.w;
            *(float4*)(sX0 + (r0 + rr) * C + j) = x0;
            *(float4*)(sX1 + (r0 + rr) * C + j) = x1;
        }
        __syncwarp();
    }

    // ---- attention branch (shared code for m / d) ----
    // t = x_last @ M; s0 = t.x_first; s1 = t.x_last; u = w0*x_first + w1*x_last (in place)
    auto attn_scores_u = [&](const float* sFirst, float* sLast) {
        float T[RPW][4] = {};
        const float4* w4 = (const float4*)sW;
#pragma unroll 2
        for (int k = 0; k < C; k++) {
            float4 wv = w4[k * 32 + lane];
#pragma unroll
            for (int rr = 0; rr < RPW; rr++) {
                float x = sLast[(r0 + rr) * C + k];
                T[rr][0] += x * wv.x; T[rr][1] += x * wv.y;
                T[rr][2] += x * wv.z; T[rr][3] += x * wv.w;
            }
        }
        int j = lane * 4;
#pragma unroll
        for (int rr = 0; rr < RPW; rr++) {
            float4 f4 = *(const float4*)(sFirst + (r0 + rr) * C + j);
            float4 l4 = *(const float4*)(sLast + (r0 + rr) * C + j);
            float s0 = T[rr][0] * f4.x + T[rr][1] * f4.y + T[rr][2] * f4.z + T[rr][3] * f4.w;
            float s1 = T[rr][0] * l4.x + T[rr][1] * l4.y + T[rr][2] * l4.z + T[rr][3] * l4.w;
#pragma unroll
            for (int o = 16; o; o >>= 1) {
                s0 += __shfl_xor_sync(~0u, s0, o);
                s1 += __shfl_xor_sync(~0u, s1, o);
            }
            float mx = fmaxf(s0, s1);
            float e0 = expf(s0 - mx), e1 = expf(s1 - mx);
            float inv = 1.f / (e0 + e1);
            float w0 = e0 * inv, w1 = e1 * inv;
            float4 u;
            u.x = w0 * f4.x + w1 * l4.x;
            u.y = w0 * f4.y + w1 * l4.y;
            u.z = w0 * f4.z + w1 * l4.z;
            u.w = w0 * f4.w + w1 * l4.w;
            *(float4*)(sLast + (r0 + rr) * C + j) = u;
        }
        __syncwarp();
    };

    // u @ Wv -> overwrite sBuf rows with LA output
    auto matvec_inplace = [&](float* sBuf) {
        float Acc[RPW][4] = {};
        const float4* w4 = (const float4*)sW;
#pragma unroll 2
        for (int k = 0; k < C; k++) {
            float4 wv = w4[k * 32 + lane];
#pragma unroll
            for (int rr = 0; rr < RPW; rr++) {
                float x = sBuf[(r0 + rr) * C + k];
                Acc[rr][0] += x * wv.x; Acc[rr][1] += x * wv.y;
                Acc[rr][2] += x * wv.z; Acc[rr][3] += x * wv.w;
            }
        }
        __syncwarp();
        int j = lane * 4;
#pragma unroll
        for (int rr = 0; rr < RPW; rr++) {
            *(float4*)(sBuf + (r0 + rr) * C + j) =
                make_float4(Acc[rr][0], Acc[rr][1], Acc[rr][2], Acc[rr][3]);
        }
        __syncwarp();
    };

    // m-branch: layers [em, x1_0], query = x1_0
    load_w(g_Mm);
    attn_scores_u(sEM, sX0);
    load_w(Wv_m);
    matvec_inplace(sX0);   // sX0 now holds mLA

    // d-branch: layers [ed, x1_1], query = x1_1
    load_w(g_Md);
    attn_scores_u(sED, sX1);
    load_w(Wv_d);
    matvec_inplace(sX1);   // sX1 now holds dLA

    // ---- head: h = relu((mLA*dLA) @ W1); pre = h . W2; sigmoid ----
    load_w(W1);
    {
        float H[RPW][4] = {};
        const float4* w4 = (const float4*)sW;
#pragma unroll 2
        for (int k = 0; k < C; k++) {
            float4 wv = w4[k * 32 + lane];
#pragma unroll
            for (int rr = 0; rr < RPW; rr++) {
                float ne = sX0[(r0 + rr) * C + k] * sX1[(r0 + rr) * C + k];
                H[rr][0] += ne * wv.x; H[rr][1] += ne * wv.y;
                H[rr][2] += ne * wv.z; H[rr][3] += ne * wv.w;
            }
        }
        int j = lane * 4;
#pragma unroll
        for (int rr = 0; rr < RPW; rr++) {
            float p = fmaxf(H[rr][0], 0.f) * sW2[j]
                    + fmaxf(H[rr][1], 0.f) * sW2[j + 1]
                    + fmaxf(H[rr][2], 0.f) * sW2[j + 2]
                    + fmaxf(H[rr][3], 0.f) * sW2[j + 3];
#pragma unroll
            for (int o = 16; o; o >>= 1) p += __shfl_xor_sync(~0u, p, o);
            if (lane == 0)
                out[base + r0 + rr] = 1.f / (1.f + expf(-p));
        }
    }
}

// ---------------------------------------------------------------------------
extern "C" void kernel_launch(void* const* d_in, const int* in_sizes, int n_in,
                              void* d_out, int out_size) {
    const float* em    = (const float*)d_in[0];
    const float* ed    = (const float*)d_in[1];
    const float* W_gcn = (const float*)d_in[2];
    const float* Wq_m  = (const float*)d_in[3];
    const float* Wk_m  = (const float*)d_in[4];
    const float* Wv_m  = (const float*)d_in[5];
    const float* Wq_d  = (const float*)d_in[6];
    const float* Wk_d  = (const float*)d_in[7];
    const float* Wv_d  = (const float*)d_in[8];
    const float* W1    = (const float*)d_in[9];
    const float* W2    = (const float*)d_in[10];
    float* out = (float*)d_out;

    const int B = in_sizes[0] / C;           // 262144
    const int smem_bytes = (4 * TILE * C + C * C + C) * (int)sizeof(float);  // 197120

    precompute_M_kernel<<<dim3(C, 2), C>>>(Wq_m, Wk_m, Wq_d, Wk_d);

    cudaFuncSetAttribute(fused_kernel,
                         cudaFuncAttributeMaxDynamicSharedMemorySize, smem_bytes);
    fused_kernel<<<B / TILE, THREADS, smem_bytes>>>(em, ed, W_gcn, Wv_m, Wv_d,
                                                    W1, W2, out);
}